// round 2
// baseline (speedup 1.0000x reference)
#include <cuda_runtime.h>
#include <cstdint>

#define Bz   64
#define Tz   8192
#define Hz   10
#define CINz 64
#define XCz  66
#define FPAD 12
#define NSEG 128
#define SEGL 64
#define WARM 32

// ---------------- scratch (device globals; no runtime allocation) ----------
__device__ __align__(16) float    g_front[Bz * Tz * FPAD];   // front-end currents [b][t][12]
__device__ __align__(16) unsigned g_maskf[Bz * Tz];          // front spike masks (10 bits)
__device__ __align__(16) unsigned g_maskz[Bz * Tz];          // LSNN spike masks (10 bits)
__device__ __align__(16) float    g_tab_rec[1024 * Hz];      // z @ w_rec^T LUT
__device__ __align__(16) float    g_tab_inlo[32 * Hz];       // spikes @ w_in^T LUT (low 5 bits)
__device__ __align__(16) float    g_tab_inhi[32 * Hz];       // (high 5 bits)
__device__ __align__(16) float    g_tab_cls[1024 * 2];       // z @ w_cls^T + b_cls LUT

// ---------------- k0: build LUTs, zero output ------------------------------
__global__ void k0_tables(const float* __restrict__ w_in, const float* __restrict__ w_rec,
                          const float* __restrict__ w_cls, const float* __restrict__ b_cls,
                          float* __restrict__ out) {
    int m = threadIdx.x;  // 0..1023
    #pragma unroll
    for (int o = 0; o < Hz; o++) {
        float a = 0.f;
        #pragma unroll
        for (int h = 0; h < Hz; h++)
            if ((m >> h) & 1) a += w_rec[o * Hz + h];
        g_tab_rec[m * Hz + o] = a;
    }
    #pragma unroll
    for (int o = 0; o < 2; o++) {
        float a = 0.f;
        #pragma unroll
        for (int h = 0; h < Hz; h++)
            if ((m >> h) & 1) a += w_cls[o * Hz + h];
        g_tab_cls[m * 2 + o] = a + b_cls[o];
    }
    if (m < 32) {
        #pragma unroll
        for (int o = 0; o < Hz; o++) {
            float lo = 0.f, hi = 0.f;
            #pragma unroll
            for (int h = 0; h < 5; h++) if ((m >> h) & 1) lo += w_in[o * Hz + h];
            #pragma unroll
            for (int h = 0; h < 5; h++) if ((m >> h) & 1) hi += w_in[o * Hz + 5 + h];
            g_tab_inlo[m * Hz + o] = lo;
            g_tab_inhi[m * Hz + o] = hi;
        }
    }
    if (m < Bz * 2) out[m] = 0.f;   // d_out is poisoned; k3 accumulates atomically
}

// ---------------- k1a: front GEMM  front[b][t][h] = w_front @ eeg + b_front -
__global__ void k1a_front(const float* __restrict__ x,
                          const float* __restrict__ w_front,
                          const float* __restrict__ b_front) {
    __shared__ float ws[Hz * CINz];
    __shared__ float bs[Hz];
    int b = blockIdx.y, t0 = blockIdx.x * 256, tid = threadIdx.x;
    for (int i = tid; i < Hz * CINz; i += 256) ws[i] = w_front[i];
    if (tid < Hz) bs[tid] = b_front[tid];
    __syncthreads();
    int t = t0 + tid;
    const float* xp = x + ((size_t)b * XCz + 1) * Tz + t;   // skip AUD channel 0
    float acc[Hz];
    #pragma unroll
    for (int h = 0; h < Hz; h++) acc[h] = 0.f;
    for (int c = 0; c < CINz; c++) {
        float v = __ldg(xp + (size_t)c * Tz);
        #pragma unroll
        for (int h = 0; h < Hz; h++) acc[h] = fmaf(ws[h * CINz + c], v, acc[h]);
    }
    float* fp = g_front + ((size_t)b * Tz + t) * FPAD;
    #pragma unroll
    for (int h = 0; h < Hz; h++) fp[h] = acc[h] + bs[h];
}

// ---------------- k1b: front LIF, exact via 32-step warmup segmentation ----
__global__ void k1b_lif() {
    int idx = blockIdx.x * blockDim.x + threadIdx.x;   // 0..8191
    int b = idx >> 7, seg = idx & (NSEG - 1);
    int t0 = seg * SEGL;
    int ts = (seg == 0) ? 0 : (t0 - WARM);
    float u[Hz];
    bool  o[Hz];
    #pragma unroll
    for (int h = 0; h < Hz; h++) { u[h] = 0.f; o[h] = false; }
    for (int t = ts; t < t0 + SEGL; t++) {
        const float* fp = g_front + ((size_t)b * Tz + t) * FPAD;
        float4 xa = *(const float4*)(fp);
        float4 xb = *(const float4*)(fp + 4);
        float2 xc = *(const float2*)(fp + 8);
        float xv[Hz] = {xa.x, xa.y, xa.z, xa.w, xb.x, xb.y, xb.z, xb.w, xc.x, xc.y};
        unsigned m = 0;
        #pragma unroll
        for (int h = 0; h < Hz; h++) {
            // u = 0.25*u*(1-o) + x ; spike -> u = x exactly
            u[h] = o[h] ? xv[h] : fmaf(0.25f, u[h], xv[h]);
            o[h] = (u[h] > 0.2f);          // spike_rect(u - VTH)
            m |= (o[h] ? 1u : 0u) << h;
        }
        if (t >= t0) g_maskf[b * Tz + t] = m;
    }
}

// ---------------- k2: exact sequential LSNN scan (warp per batch) ----------
__global__ void __launch_bounds__(32, 1) k2_scan() {
    __shared__ float s_rec[1024 * Hz];
    __shared__ float s_inlo[32 * Hz];
    __shared__ float s_inhi[32 * Hz];
    int b = blockIdx.x, lane = threadIdx.x;
    {
        const float4* src = (const float4*)g_tab_rec;
        float4* dst = (float4*)s_rec;
        for (int i = lane; i < (1024 * Hz) / 4; i += 32) dst[i] = src[i];
        for (int i = lane; i < 32 * Hz; i += 32) { s_inlo[i] = g_tab_inlo[i]; s_inhi[i] = g_tab_inhi[i]; }
    }
    __syncwarp();
    int ln = (lane < Hz) ? lane : 0;
    const uint4* mfp = (const uint4*)(g_maskf + (size_t)b * Tz);
    uint4* mzp = (uint4*)(g_maskz + (size_t)b * Tz);
    const int NV = Tz / 4;

    float v = 0.f, ii = 0.f;
    unsigned mz = 0;
    uint4 c0 = mfp[0];
    uint4 c1 = mfp[1];
    for (int j = 0; j < NV; j++) {
        int j2 = (j + 2 < NV) ? j + 2 : NV - 1;
        uint4 nxt = mfp[j2];                     // prefetch ahead (covers L2 latency)
        unsigned mfs[4] = {c0.x, c0.y, c0.z, c0.w};
        unsigned zout[4];
        #pragma unroll
        for (int k = 0; k < 4; k++) {
            unsigned mf = mfs[k];
            float xin = s_inlo[(mf & 31u) * Hz + ln] + s_inhi[((mf >> 5) & 31u) * Hz + ln];
            float rec = s_rec[mz * Hz + ln];              // critical-path LDS
            float ij  = (ii + xin) + rec;                 // i_jump
            float vdec = fmaf(0.1f, ij - v, v);           // v + 0.1*(-v + i_jump)
            bool  z    = (vdec > 0.2f);                   // b_dec stays exactly VTH
            ii = ij - 0.2f * ij;                          // i_dec (reference op order)
            v  = z ? 0.f : vdec;                          // (1-z)*v_dec
            mz = __ballot_sync(0xFFFFFFFFu, z) & 0x3FFu;
            zout[k] = mz;
        }
        if (lane == 0) mzp[j] = make_uint4(zout[0], zout[1], zout[2], zout[3]);
        c0 = c1; c1 = nxt;
    }
}

// ---------------- k3: classifier LIF + time-average (exact 32-step warmup) -
__global__ void k3_cls(float* __restrict__ out) {
    __shared__ float s_cls[1024 * 2];
    {
        int tid = threadIdx.x;
        const float4* src = (const float4*)g_tab_cls;
        float4* dst = (float4*)s_cls;
        for (int i = tid; i < (1024 * 2) / 4; i += 128) dst[i] = src[i];
    }
    __syncthreads();
    int idx = blockIdx.x * blockDim.x + threadIdx.x;   // 0..8191
    int b = idx >> 7, seg = idx & (NSEG - 1);
    int t0 = seg * SEGL;
    int ts = (seg == 0) ? 0 : (t0 - WARM);
    float u0 = 0.f, u1 = 0.f;
    bool  o0 = false, o1 = false;
    int   c0 = 0, c1 = 0;
    const unsigned* mzp = g_maskz + (size_t)b * Tz;
    for (int t = ts; t < t0 + SEGL; t++) {
        unsigned mz = mzp[t];
        float x0 = s_cls[mz * 2 + 0];
        float x1 = s_cls[mz * 2 + 1];
        u0 = o0 ? x0 : fmaf(0.25f, u0, x0);
        u1 = o1 ? x1 : fmaf(0.25f, u1, x1);
        o0 = (u0 > 0.2f);
        o1 = (u1 > 0.2f);
        if (t >= t0) { c0 += o0 ? 1 : 0; c1 += o1 ? 1 : 0; }
    }
    // counts/8192 are exact multiples of 2^-13; float atomic sums stay exact
    atomicAdd(&out[b * 2 + 0], (float)c0 * (1.0f / (float)Tz));
    atomicAdd(&out[b * 2 + 1], (float)c1 * (1.0f / (float)Tz));
}

extern "C" void kernel_launch(void* const* d_in, const int* in_sizes, int n_in,
                              void* d_out, int out_size) {
    const float* x       = (const float*)d_in[0];
    const float* w_front = (const float*)d_in[1];
    const float* b_front = (const float*)d_in[2];
    const float* w_in    = (const float*)d_in[3];
    const float* w_rec   = (const float*)d_in[4];
    const float* w_cls   = (const float*)d_in[5];
    const float* b_cls   = (const float*)d_in[6];
    float* out = (float*)d_out;

    k0_tables<<<1, 1024>>>(w_in, w_rec, w_cls, b_cls, out);
    k1a_front<<<dim3(Tz / 256, Bz), 256>>>(x, w_front, b_front);
    k1b_lif<<<Bz, 128>>>();
    k2_scan<<<Bz, 32>>>();
    k3_cls<<<Bz, 128>>>(out);
}

// round 4
// speedup vs baseline: 1.4576x; 1.4576x over previous
#include <cuda_runtime.h>
#include <cstdint>

#define Bz   64
#define Tz   8192
#define Hz   10
#define CINz 64
#define XCz  66
#define FPAD 12
// front/cls LIF segmentation (decay 0.25 -> 32-step warmup is exact)
#define NSEG 128
#define SEGL 64
#define WARM 32
// LSNN segmentation: 4 segments of 2048, warmup 2048 (seg1 warmup starts at t=0 -> exact)
#define NS2   4
#define SEGL2 2048
#define WARM2 2048
#define WPB   4            // warps (segments) per block in k2

// ---------------- scratch (device globals; no runtime allocation) ----------
__device__ __align__(16) float    g_front[Bz * Tz * FPAD];
__device__ __align__(16) unsigned g_maskf[Bz * Tz];
__device__ __align__(16) unsigned g_maskz[Bz * Tz];
__device__ __align__(16) float    g_tab_rec[1024 * Hz];
__device__ __align__(16) float    g_tab_inlo[32 * Hz];
__device__ __align__(16) float    g_tab_inhi[32 * Hz];
__device__ __align__(16) float    g_tab_cls[1024 * 2];

// ---------------- k0: build LUTs, zero output ------------------------------
__global__ void k0_tables(const float* __restrict__ w_in, const float* __restrict__ w_rec,
                          const float* __restrict__ w_cls, const float* __restrict__ b_cls,
                          float* __restrict__ out) {
    int m = threadIdx.x;  // 0..1023
    #pragma unroll
    for (int o = 0; o < Hz; o++) {
        float a = 0.f;
        #pragma unroll
        for (int h = 0; h < Hz; h++)
            if ((m >> h) & 1) a += w_rec[o * Hz + h];
        g_tab_rec[m * Hz + o] = a;
    }
    #pragma unroll
    for (int o = 0; o < 2; o++) {
        float a = 0.f;
        #pragma unroll
        for (int h = 0; h < Hz; h++)
            if ((m >> h) & 1) a += w_cls[o * Hz + h];
        g_tab_cls[m * 2 + o] = a + b_cls[o];
    }
    if (m < 32) {
        #pragma unroll
        for (int o = 0; o < Hz; o++) {
            float lo = 0.f, hi = 0.f;
            #pragma unroll
            for (int h = 0; h < 5; h++) if ((m >> h) & 1) lo += w_in[o * Hz + h];
            #pragma unroll
            for (int h = 0; h < 5; h++) if ((m >> h) & 1) hi += w_in[o * Hz + 5 + h];
            g_tab_inlo[m * Hz + o] = lo;
            g_tab_inhi[m * Hz + o] = hi;
        }
    }
    if (m < Bz * 2) out[m] = 0.f;
}

// ---------------- k1a: front GEMM ------------------------------------------
__global__ void k1a_front(const float* __restrict__ x,
                          const float* __restrict__ w_front,
                          const float* __restrict__ b_front) {
    __shared__ float ws[Hz * CINz];
    __shared__ float bs[Hz];
    int b = blockIdx.y, t0 = blockIdx.x * 256, tid = threadIdx.x;
    for (int i = tid; i < Hz * CINz; i += 256) ws[i] = w_front[i];
    if (tid < Hz) bs[tid] = b_front[tid];
    __syncthreads();
    int t = t0 + tid;
    const float* xp = x + ((size_t)b * XCz + 1) * Tz + t;   // skip AUD channel 0
    float acc[Hz];
    #pragma unroll
    for (int h = 0; h < Hz; h++) acc[h] = 0.f;
    for (int c = 0; c < CINz; c++) {
        float v = __ldg(xp + (size_t)c * Tz);
        #pragma unroll
        for (int h = 0; h < Hz; h++) acc[h] = fmaf(ws[h * CINz + c], v, acc[h]);
    }
    float* fp = g_front + ((size_t)b * Tz + t) * FPAD;
    #pragma unroll
    for (int h = 0; h < Hz; h++) fp[h] = acc[h] + bs[h];
}

// ---------------- k1b: front LIF (exact 32-step warmup) --------------------
__global__ void k1b_lif() {
    int idx = blockIdx.x * blockDim.x + threadIdx.x;   // 0..8191
    int b = idx >> 7, seg = idx & (NSEG - 1);
    int t0 = seg * SEGL;
    int ts = (seg == 0) ? 0 : (t0 - WARM);
    float u[Hz];
    bool  o[Hz];
    #pragma unroll
    for (int h = 0; h < Hz; h++) { u[h] = 0.f; o[h] = false; }
    for (int t = ts; t < t0 + SEGL; t++) {
        const float* fp = g_front + ((size_t)b * Tz + t) * FPAD;
        float4 xa = *(const float4*)(fp);
        float4 xb = *(const float4*)(fp + 4);
        float2 xc = *(const float2*)(fp + 8);
        float xv[Hz] = {xa.x, xa.y, xa.z, xa.w, xb.x, xb.y, xb.z, xb.w, xc.x, xc.y};
        unsigned m = 0;
        #pragma unroll
        for (int h = 0; h < Hz; h++) {
            u[h] = o[h] ? xv[h] : fmaf(0.25f, u[h], xv[h]);
            o[h] = (u[h] > 0.2f);
            m |= (o[h] ? 1u : 0u) << h;
        }
        if (t >= t0) g_maskf[b * Tz + t] = m;
    }
}

// ---------------- k2: segmented LSNN scan (warp per (batch, segment)) ------
// Per-step critical chain: VOTE -> IMAD -> LDS(rec) -> FSETP -> VOTE.
// Spike test hoisted to "rec > thr", thr = (2 - 9v) - pre computed off-path.
__global__ void __launch_bounds__(WPB * 32, 1) k2_scan() {
    __shared__ float s_rec[1024 * Hz];
    __shared__ float s_inlo[32 * Hz];
    __shared__ float s_inhi[32 * Hz];
    int tid = threadIdx.x, lane = tid & 31, wrp = tid >> 5;
    {
        const float4* src = (const float4*)g_tab_rec;
        float4* dst = (float4*)s_rec;
        for (int i = tid; i < (1024 * Hz) / 4; i += WPB * 32) dst[i] = src[i];
        for (int i = tid; i < 32 * Hz; i += WPB * 32) { s_inlo[i] = g_tab_inlo[i]; s_inhi[i] = g_tab_inhi[i]; }
    }
    __syncthreads();

    int w   = blockIdx.x * WPB + wrp;        // 0..Bz*NS2-1
    int b   = w >> 2;                        // NS2 = 4
    int seg = w & (NS2 - 1);
    int t0  = seg * SEGL2;
    int ts  = (t0 - WARM2 > 0) ? (t0 - WARM2) : 0;

    int ln = (lane < Hz) ? lane : 0;
    const uint4* mfp = (const uint4*)(g_maskf + (size_t)b * Tz);
    uint4* mzp = (uint4*)(g_maskz + (size_t)b * Tz);
    int js = ts >> 2, jw = t0 >> 2, je = (t0 + SEGL2) >> 2;

    float v = 0.f, ii = 0.f;
    unsigned mz = 0;
    // thr/pre for the first step (v=0, ii=0)
    uint4 c0 = mfp[js];
    uint4 c1 = mfp[js + 1];
    for (int j = js; j < je; j++) {
        int j2 = (j + 2 < je) ? j + 2 : je - 1;
        uint4 nxt = mfp[j2];
        unsigned mfs[4] = {c0.x, c0.y, c0.z, c0.w};
        unsigned zout[4];
        #pragma unroll
        for (int k = 0; k < 4; k++) {
            unsigned mf = mfs[k];
            float xin = s_inlo[(mf & 31u) * Hz + ln] + s_inhi[((mf >> 5) & 31u) * Hz + ln];
            float pre = ii + xin;                          // off critical path
            float thr = fmaf(-9.0f, v, 2.0f) - pre;        // off critical path
            float rec = s_rec[mz * Hz + ln];               // critical LDS
            bool  z   = (rec > thr);                       // == (vdec > 0.2)
            mz = __ballot_sync(0xFFFFFFFFu, z) & 0x3FFu;   // critical VOTE
            // state updates execute in the shadow of next step's LDS/VOTE
            float ij   = pre + rec;                        // i_jump
            float vdec = fmaf(0.1f, ij, 0.9f * v);
            ii = fmaf(-0.2f, ij, ij);                      // i_dec
            v  = z ? 0.f : vdec;
            zout[k] = mz;
        }
        if (lane == 0 && j >= jw) mzp[j] = make_uint4(zout[0], zout[1], zout[2], zout[3]);
        c0 = c1; c1 = nxt;
    }
}

// ---------------- k3: classifier LIF + time-average (exact 32-step warmup) -
__global__ void k3_cls(float* __restrict__ out) {
    __shared__ float s_cls[1024 * 2];
    {
        int tid = threadIdx.x;
        const float4* src = (const float4*)g_tab_cls;
        float4* dst = (float4*)s_cls;
        for (int i = tid; i < (1024 * 2) / 4; i += 128) dst[i] = src[i];
    }
    __syncthreads();
    int idx = blockIdx.x * blockDim.x + threadIdx.x;   // 0..8191
    int b = idx >> 7, seg = idx & (NSEG - 1);
    int t0 = seg * SEGL;
    int ts = (seg == 0) ? 0 : (t0 - WARM);
    float u0 = 0.f, u1 = 0.f;
    bool  o0 = false, o1 = false;
    int   c0 = 0, c1 = 0;
    const unsigned* mzp = g_maskz + (size_t)b * Tz;
    for (int t = ts; t < t0 + SEGL; t++) {
        unsigned mz = mzp[t];
        float x0 = s_cls[mz * 2 + 0];
        float x1 = s_cls[mz * 2 + 1];
        u0 = o0 ? x0 : fmaf(0.25f, u0, x0);
        u1 = o1 ? x1 : fmaf(0.25f, u1, x1);
        o0 = (u0 > 0.2f);
        o1 = (u1 > 0.2f);
        if (t >= t0) { c0 += o0 ? 1 : 0; c1 += o1 ? 1 : 0; }
    }
    atomicAdd(&out[b * 2 + 0], (float)c0 * (1.0f / (float)Tz));
    atomicAdd(&out[b * 2 + 1], (float)c1 * (1.0f / (float)Tz));
}

extern "C" void kernel_launch(void* const* d_in, const int* in_sizes, int n_in,
                              void* d_out, int out_size) {
    const float* x       = (const float*)d_in[0];
    const float* w_front = (const float*)d_in[1];
    const float* b_front = (const float*)d_in[2];
    const float* w_in    = (const float*)d_in[3];
    const float* w_rec   = (const float*)d_in[4];
    const float* w_cls   = (const float*)d_in[5];
    const float* b_cls   = (const float*)d_in[6];
    float* out = (float*)d_out;

    k0_tables<<<1, 1024>>>(w_in, w_rec, w_cls, b_cls, out);
    k1a_front<<<dim3(Tz / 256, Bz), 256>>>(x, w_front, b_front);
    k1b_lif<<<Bz, 128>>>();
    k2_scan<<<(Bz * NS2) / WPB, WPB * 32>>>();
    k3_cls<<<Bz, 128>>>(out);
}

// round 5
// speedup vs baseline: 1.8940x; 1.2994x over previous
#include <cuda_runtime.h>
#include <cstdint>

#define Bz   64
#define Tz   8192
#define Hz   10
#define CINz 64
#define XCz  66
#define FPAD 12
// front/cls LIF segmentation (decay 0.25 -> 32-step warmup is exact)
#define NSEG 128
#define SEGL 64
#define WARM 32
// LSNN segmentation: 16 segments of 512, warmup 2048 (segs 0-4 exact)
#define NS2   16
#define SEGL2 512
#define WARM2 2048
#define WPB   8            // warps per block in k2 (128 blocks -> single wave)

// ---------------- scratch (device globals; no runtime allocation) ----------
__device__ __align__(16) float    g_front[Bz * Tz * FPAD];
__device__ __align__(16) unsigned g_maskf[Bz * Tz];
__device__ __align__(16) unsigned g_maskz[Bz * Tz];
__device__ __align__(16) float    g_tab_rec[1024 * Hz];
__device__ __align__(16) float    g_tab_inlo[32 * 32];   // padded: lanes>=10 get -5e29
__device__ __align__(16) float    g_tab_inhi[32 * 32];
__device__ __align__(16) float    g_tab_cls[1024 * 2];

// ---------------- k0: build LUTs, zero output ------------------------------
__global__ void k0_tables(const float* __restrict__ w_in, const float* __restrict__ w_rec,
                          const float* __restrict__ w_cls, const float* __restrict__ b_cls,
                          float* __restrict__ out) {
    int m = threadIdx.x;  // 0..1023
    #pragma unroll
    for (int o = 0; o < Hz; o++) {
        float a = 0.f;
        #pragma unroll
        for (int h = 0; h < Hz; h++)
            if ((m >> h) & 1) a += w_rec[o * Hz + h];
        g_tab_rec[m * Hz + o] = a;
    }
    #pragma unroll
    for (int o = 0; o < 2; o++) {
        float a = 0.f;
        #pragma unroll
        for (int h = 0; h < Hz; h++)
            if ((m >> h) & 1) a += w_cls[o * Hz + h];
        g_tab_cls[m * 2 + o] = a + b_cls[o];
    }
    if (m < 32) {
        // padded 32-lane tables; sentinel forces lanes 10..31 to never spike
        for (int l = 0; l < 32; l++) {
            float lo, hi;
            if (l < Hz) {
                lo = 0.f; hi = 0.f;
                #pragma unroll
                for (int h = 0; h < 5; h++) if ((m >> h) & 1) lo += w_in[l * Hz + h];
                #pragma unroll
                for (int h = 0; h < 5; h++) if ((m >> h) & 1) hi += w_in[l * Hz + 5 + h];
            } else {
                lo = -5e29f; hi = -5e29f;
            }
            g_tab_inlo[m * 32 + l] = lo;
            g_tab_inhi[m * 32 + l] = hi;
        }
    }
    if (m < Bz * 2) out[m] = 0.f;
}

// ---------------- k1a: front GEMM ------------------------------------------
__global__ void k1a_front(const float* __restrict__ x,
                          const float* __restrict__ w_front,
                          const float* __restrict__ b_front) {
    __shared__ float ws[Hz * CINz];
    __shared__ float bs[Hz];
    int b = blockIdx.y, t0 = blockIdx.x * 256, tid = threadIdx.x;
    for (int i = tid; i < Hz * CINz; i += 256) ws[i] = w_front[i];
    if (tid < Hz) bs[tid] = b_front[tid];
    __syncthreads();
    int t = t0 + tid;
    const float* xp = x + ((size_t)b * XCz + 1) * Tz + t;   // skip AUD channel 0
    float acc[Hz];
    #pragma unroll
    for (int h = 0; h < Hz; h++) acc[h] = 0.f;
    for (int c = 0; c < CINz; c++) {
        float v = __ldg(xp + (size_t)c * Tz);
        #pragma unroll
        for (int h = 0; h < Hz; h++) acc[h] = fmaf(ws[h * CINz + c], v, acc[h]);
    }
    float* fp = g_front + ((size_t)b * Tz + t) * FPAD;
    #pragma unroll
    for (int h = 0; h < Hz; h++) fp[h] = acc[h] + bs[h];
}

// ---------------- k1b: front LIF (exact 32-step warmup) --------------------
__global__ void k1b_lif() {
    int idx = blockIdx.x * blockDim.x + threadIdx.x;   // 0..8191
    int b = idx >> 7, seg = idx & (NSEG - 1);
    int t0 = seg * SEGL;
    int ts = (seg == 0) ? 0 : (t0 - WARM);
    float u[Hz];
    bool  o[Hz];
    #pragma unroll
    for (int h = 0; h < Hz; h++) { u[h] = 0.f; o[h] = false; }
    for (int t = ts; t < t0 + SEGL; t++) {
        const float* fp = g_front + ((size_t)b * Tz + t) * FPAD;
        float4 xa = *(const float4*)(fp);
        float4 xb = *(const float4*)(fp + 4);
        float2 xc = *(const float2*)(fp + 8);
        float xv[Hz] = {xa.x, xa.y, xa.z, xa.w, xb.x, xb.y, xb.z, xb.w, xc.x, xc.y};
        unsigned m = 0;
        #pragma unroll
        for (int h = 0; h < Hz; h++) {
            u[h] = o[h] ? xv[h] : fmaf(0.25f, u[h], xv[h]);
            o[h] = (u[h] > 0.2f);
            m |= (o[h] ? 1u : 0u) << h;
        }
        if (t >= t0) g_maskf[b * Tz + t] = m;
    }
}

// ---------------- k2: segmented LSNN scan (warp per (batch, segment)) ------
// Critical chain: VOTE -> IMAD -> LDS(rec) -> FSETP -> VOTE.
// Lanes >= 10 are poisoned (xin = -1e30 -> never spike) so ballot needs no mask.
__global__ void __launch_bounds__(WPB * 32, 1) k2_scan() {
    __shared__ float s_rec[1024 * Hz];
    __shared__ float s_inlo[32 * 32];
    __shared__ float s_inhi[32 * 32];
    int tid = threadIdx.x, lane = tid & 31, wrp = tid >> 5;
    {
        const float4* src = (const float4*)g_tab_rec;
        float4* dst = (float4*)s_rec;
        for (int i = tid; i < (1024 * Hz) / 4; i += WPB * 32) dst[i] = src[i];
        for (int i = tid; i < 32 * 32; i += WPB * 32) { s_inlo[i] = g_tab_inlo[i]; s_inhi[i] = g_tab_inhi[i]; }
    }
    __syncthreads();

    int w   = blockIdx.x * WPB + wrp;        // 0..Bz*NS2-1
    int b   = w >> 4;                        // NS2 = 16
    int seg = w & (NS2 - 1);
    int t0  = seg * SEGL2;
    int ts  = (t0 - WARM2 > 0) ? (t0 - WARM2) : 0;

    int ln = (lane < Hz) ? lane : 0;         // rec row clamped (harmless; poisoned lanes never spike)
    const uint4* mfp = (const uint4*)(g_maskf + (size_t)b * Tz);
    uint4* mzp = (uint4*)(g_maskz + (size_t)b * Tz);
    int js = ts >> 2, jw = t0 >> 2, je = (t0 + SEGL2) >> 2;

    float v = 0.f, ii = 0.f;
    unsigned mz = 0;
    uint4 c0 = mfp[js];
    uint4 c1 = mfp[js + 1];
    for (int j = js; j < je; j++) {
        int j2 = (j + 2 < je) ? j + 2 : je - 1;
        uint4 nxt = mfp[j2];
        unsigned mfs[4] = {c0.x, c0.y, c0.z, c0.w};
        unsigned zout[4];
        #pragma unroll
        for (int k = 0; k < 4; k++) {
            unsigned mf = mfs[k];
            float xin = s_inlo[(mf & 31u) * 32 + lane] + s_inhi[((mf >> 5) & 31u) * 32 + lane];
            float pre = ii + xin;                          // off critical path
            float thr = fmaf(-9.0f, v, 2.0f) - pre;        // off critical path
            float rec = s_rec[mz * Hz + ln];               // critical LDS
            bool  z   = (rec > thr);                       // == (vdec > 0.2)
            mz = __ballot_sync(0xFFFFFFFFu, z);            // high bits 0 by construction
            // state updates in the shadow of next step's LDS/VOTE
            float ij   = pre + rec;                        // i_jump
            float vdec = fmaf(0.1f, ij, 0.9f * v);
            ii = fmaf(-0.2f, ij, ij);                      // i_dec
            v  = z ? 0.f : vdec;
            zout[k] = mz;
        }
        if (lane == 0 && j >= jw) mzp[j] = make_uint4(zout[0], zout[1], zout[2], zout[3]);
        c0 = c1; c1 = nxt;
    }
}

// ---------------- k3: classifier LIF + time-average (exact 32-step warmup) -
__global__ void k3_cls(float* __restrict__ out) {
    __shared__ float s_cls[1024 * 2];
    {
        int tid = threadIdx.x;
        const float4* src = (const float4*)g_tab_cls;
        float4* dst = (float4*)s_cls;
        for (int i = tid; i < (1024 * 2) / 4; i += 128) dst[i] = src[i];
    }
    __syncthreads();
    int idx = blockIdx.x * blockDim.x + threadIdx.x;   // 0..8191
    int b = idx >> 7, seg = idx & (NSEG - 1);
    int t0 = seg * SEGL;
    int ts = (seg == 0) ? 0 : (t0 - WARM);
    float u0 = 0.f, u1 = 0.f;
    bool  o0 = false, o1 = false;
    int   c0 = 0, c1 = 0;
    const unsigned* mzp = g_maskz + (size_t)b * Tz;
    for (int t = ts; t < t0 + SEGL; t++) {
        unsigned mz = mzp[t];
        float x0 = s_cls[mz * 2 + 0];
        float x1 = s_cls[mz * 2 + 1];
        u0 = o0 ? x0 : fmaf(0.25f, u0, x0);
        u1 = o1 ? x1 : fmaf(0.25f, u1, x1);
        o0 = (u0 > 0.2f);
        o1 = (u1 > 0.2f);
        if (t >= t0) { c0 += o0 ? 1 : 0; c1 += o1 ? 1 : 0; }
    }
    atomicAdd(&out[b * 2 + 0], (float)c0 * (1.0f / (float)Tz));
    atomicAdd(&out[b * 2 + 1], (float)c1 * (1.0f / (float)Tz));
}

extern "C" void kernel_launch(void* const* d_in, const int* in_sizes, int n_in,
                              void* d_out, int out_size) {
    const float* x       = (const float*)d_in[0];
    const float* w_front = (const float*)d_in[1];
    const float* b_front = (const float*)d_in[2];
    const float* w_in    = (const float*)d_in[3];
    const float* w_rec   = (const float*)d_in[4];
    const float* w_cls   = (const float*)d_in[5];
    const float* b_cls   = (const float*)d_in[6];
    float* out = (float*)d_out;

    k0_tables<<<1, 1024>>>(w_in, w_rec, w_cls, b_cls, out);
    k1a_front<<<dim3(Tz / 256, Bz), 256>>>(x, w_front, b_front);
    k1b_lif<<<Bz, 128>>>();
    k2_scan<<<(Bz * NS2) / WPB, WPB * 32>>>();
    k3_cls<<<Bz, 128>>>(out);
}

// round 6
// speedup vs baseline: 1.9285x; 1.0182x over previous
#include <cuda_runtime.h>
#include <cstdint>

#define Bz   64
#define Tz   8192
#define Hz   10
#define CINz 64
#define XCz  66
// front LIF segmentation (decay 0.25 -> 32-step warmup exact)
#define TCH  256           // t-chunk per k1 block (4 segments of 64)
// LSNN segmentation: 16 segments of 512, warmup 2048 (segs 0-4 exact)
#define NS2   16
#define SEGL2 512
#define WARM2 2048
#define WPB   8            // warps per block in k2 (128 blocks -> single wave)

// ---------------- scratch (device globals; no runtime allocation) ----------
__device__ __align__(16) unsigned g_maskf[Bz * Tz];
__device__ __align__(16) float    g_tab_rec[1024 * Hz];
__device__ __align__(16) float    g_tab_inlo[32 * Hz];
__device__ __align__(16) float    g_tab_inhi[32 * Hz];
__device__ __align__(16) float    g_tab_cls[1024 * 2];

// ---------------- k0: build LUTs, zero output ------------------------------
__global__ void k0_tables(const float* __restrict__ w_in, const float* __restrict__ w_rec,
                          const float* __restrict__ w_cls, const float* __restrict__ b_cls,
                          float* __restrict__ out) {
    int m = threadIdx.x;  // 0..1023
    #pragma unroll
    for (int o = 0; o < Hz; o++) {
        float a = 0.f;
        #pragma unroll
        for (int h = 0; h < Hz; h++)
            if ((m >> h) & 1) a += w_rec[o * Hz + h];
        g_tab_rec[m * Hz + o] = a;
    }
    #pragma unroll
    for (int o = 0; o < 2; o++) {
        float a = 0.f;
        #pragma unroll
        for (int h = 0; h < Hz; h++)
            if ((m >> h) & 1) a += w_cls[o * Hz + h];
        g_tab_cls[m * 2 + o] = a + b_cls[o];
    }
    if (m < 32) {
        #pragma unroll
        for (int o = 0; o < Hz; o++) {
            float lo = 0.f, hi = 0.f;
            #pragma unroll
            for (int h = 0; h < 5; h++) if ((m >> h) & 1) lo += w_in[o * Hz + h];
            #pragma unroll
            for (int h = 0; h < 5; h++) if ((m >> h) & 1) hi += w_in[o * Hz + 5 + h];
            g_tab_inlo[m * Hz + o] = lo;
            g_tab_inhi[m * Hz + o] = hi;
        }
    }
    if (m < Bz * 2) out[m] = 0.f;
}

// ---------------- k1: fused front GEMM + LIF (per 256-t chunk) -------------
// GEMM into shared (288 t's incl. 32-step warmup region), then 4 segments x
// 10 neurons run the LIF on half-warp lanes; masks assembled via ballot.
__global__ void __launch_bounds__(256) k1_front(const float* __restrict__ x,
                                                const float* __restrict__ w_front,
                                                const float* __restrict__ b_front) {
    __shared__ float ws[Hz * CINz];
    __shared__ float bs[Hz];
    __shared__ float sf[(TCH + 32) * Hz];    // 2880 floats
    int tid = threadIdx.x, bt = blockIdx.x, b = blockIdx.y;
    for (int i = tid; i < Hz * CINz; i += 256) ws[i] = w_front[i];
    if (tid < Hz) bs[tid] = b_front[tid];
    __syncthreads();

    int base = bt * TCH - 32;
    for (int li = tid; li < TCH + 32; li += 256) {
        int t = base + li;
        if (t >= 0) {
            const float* xp = x + ((size_t)b * XCz + 1) * Tz + t;  // skip AUD ch 0
            float acc[Hz];
            #pragma unroll
            for (int h = 0; h < Hz; h++) acc[h] = 0.f;
            #pragma unroll 4
            for (int c = 0; c < CINz; c++) {
                float v = __ldg(xp + (size_t)c * Tz);
                #pragma unroll
                for (int h = 0; h < Hz; h++) acc[h] = fmaf(ws[h * CINz + c], v, acc[h]);
            }
            #pragma unroll
            for (int h = 0; h < Hz; h++) sf[li * Hz + h] = acc[h] + bs[h];
        }
    }
    __syncthreads();

    int wid = tid >> 5, lane = tid & 31;
    if (wid < 2) {
        int seg = wid * 2 + (lane >> 4);     // 0..3
        int h  = lane & 15;
        int hc = (h < Hz) ? h : Hz - 1;
        int t0s = bt * TCH + seg * 64;
        int li0 = seg * 64 + 32;
        int lis = (t0s == 0) ? li0 : li0 - 32;
        float u = 0.f; bool o = false;
        for (int li = lis; li < li0; li++) {          // warmup (no output)
            float xv = sf[li * Hz + hc];
            u = o ? xv : fmaf(0.25f, u, xv);
            o = (h < Hz) && (u > 0.2f);
        }
        unsigned* mp = g_maskf + (size_t)b * Tz + t0s;
        for (int g = 0; g < 16; g++) {
            unsigned q0, q1, q2, q3;
            #pragma unroll
            for (int kk = 0; kk < 4; kk++) {
                int li = li0 + g * 4 + kk;
                float xv = sf[li * Hz + hc];
                u = o ? xv : fmaf(0.25f, u, xv);
                o = (h < Hz) && (u > 0.2f);
                unsigned bal = __ballot_sync(0xFFFFFFFFu, o);
                unsigned mk = (lane < 16) ? (bal & 0x3FFu) : ((bal >> 16) & 0x3FFu);
                if (kk == 0) q0 = mk; else if (kk == 1) q1 = mk;
                else if (kk == 2) q2 = mk; else q3 = mk;
            }
            if (lane == 0 || lane == 16)
                *(uint4*)(mp + g * 4) = make_uint4(q0, q1, q2, q3);
        }
    }
}

// ---------------- k2: segmented LSNN scan + fused classifier ---------------
// Critical chain: VOTE -> IMAD -> LDS(rec) -> FSETP -> VOTE (~123 cyc/step).
// Lanes 10/11 run the 2-neuron classifier LIF in the chain's shadow.
__global__ void __launch_bounds__(WPB * 32, 1) k2_scan(float* __restrict__ out) {
    __shared__ float s_rec[1024 * Hz];
    __shared__ float s_inlo[32 * Hz];
    __shared__ float s_inhi[32 * Hz];
    int tid = threadIdx.x, lane = tid & 31, wrp = tid >> 5;
    {
        const float4* src = (const float4*)g_tab_rec;
        float4* dst = (float4*)s_rec;
        for (int i = tid; i < (1024 * Hz) / 4; i += WPB * 32) dst[i] = src[i];
        for (int i = tid; i < 32 * Hz; i += WPB * 32) { s_inlo[i] = g_tab_inlo[i]; s_inhi[i] = g_tab_inhi[i]; }
    }
    __syncthreads();

    int w   = blockIdx.x * WPB + wrp;        // 0..Bz*NS2-1
    int b   = w >> 4;                        // NS2 = 16
    int seg = w & (NS2 - 1);
    int t0  = seg * SEGL2;
    int ts  = (t0 - WARM2 > 0) ? (t0 - WARM2) : 0;

    int ln = (lane < Hz) ? lane : 0;
    int csel = (lane == 11) ? 1 : 0;
    const uint4* mfp = (const uint4*)(g_maskf + (size_t)b * Tz);
    int js = ts >> 2, jw = t0 >> 2, je = (t0 + SEGL2) >> 2;

    float v = 0.f, ii = 0.f;
    unsigned mz = 0;
    float uc = 0.f; bool oc = false; int cnt = 0;
    uint4 c0 = mfp[js];
    uint4 c1 = mfp[js + 1];
    for (int j = js; j < je; j++) {
        int j2 = (j + 2 < je) ? j + 2 : je - 1;
        uint4 nxt = mfp[j2];
        bool counting = (j >= jw);
        unsigned mfs[4] = {c0.x, c0.y, c0.z, c0.w};
        #pragma unroll
        for (int k = 0; k < 4; k++) {
            unsigned mf = mfs[k];
            float xin = s_inlo[(mf & 31u) * Hz + ln] + s_inhi[((mf >> 5) & 31u) * Hz + ln];
            float pre = ii + xin;                          // off critical path
            float thr = fmaf(-9.0f, v, 2.0f) - pre;        // off critical path
            float rec = s_rec[mz * Hz + ln];               // critical LDS
            bool  z   = (rec > thr);                       // == (vdec > 0.2)
            mz = __ballot_sync(0xFFFFFFFFu, z) & 0x3FFu;   // critical VOTE
            // classifier LIF (lanes 10/11 meaningful) in the chain's shadow
            float xc = __ldg(&g_tab_cls[mz * 2 + csel]);   // 8KB table, L1-hot
            uc = oc ? xc : fmaf(0.25f, uc, xc);
            oc = (uc > 0.2f);
            if (counting && oc) cnt++;
            // LSNN state updates in the shadow of next step's LDS/VOTE
            float ij   = pre + rec;                        // i_jump
            float vdec = fmaf(0.1f, ij, 0.9f * v);
            ii = fmaf(-0.2f, ij, ij);                      // i_dec
            v  = z ? 0.f : vdec;
        }
        c0 = c1; c1 = nxt;
    }
    // counts * 2^-13: every partial sum exact in fp32 atomics
    if (lane == 10) atomicAdd(&out[b * 2 + 0], (float)cnt * (1.0f / (float)Tz));
    if (lane == 11) atomicAdd(&out[b * 2 + 1], (float)cnt * (1.0f / (float)Tz));
}

extern "C" void kernel_launch(void* const* d_in, const int* in_sizes, int n_in,
                              void* d_out, int out_size) {
    const float* x       = (const float*)d_in[0];
    const float* w_front = (const float*)d_in[1];
    const float* b_front = (const float*)d_in[2];
    const float* w_in    = (const float*)d_in[3];
    const float* w_rec   = (const float*)d_in[4];
    const float* w_cls   = (const float*)d_in[5];
    const float* b_cls   = (const float*)d_in[6];
    float* out = (float*)d_out;

    k0_tables<<<1, 1024>>>(w_in, w_rec, w_cls, b_cls, out);
    k1_front<<<dim3(Tz / TCH, Bz), 256>>>(x, w_front, b_front);
    k2_scan<<<(Bz * NS2) / WPB, WPB * 32>>>(out);
}

// round 7
// speedup vs baseline: 2.1622x; 1.1212x over previous
#include <cuda_runtime.h>
#include <cstdint>

#define Bz   64
#define Tz   8192
#define Hz   10
#define CINz 64
#define XCz  66
// front LIF segmentation (decay 0.25 -> 32-step warmup exact)
#define TCH  256           // t-chunk per k1 block (4 segments of 64)
#define K1T  (TCH + 32)    // 288 threads: one GEMM row each
// LSNN segmentation: 16 segments of 512, warmup 2048 (segs 0-4 exact)
#define NS2   16
#define SEGL2 512
#define WARM2 2048
#define WPB   8            // warps per block in k2 (128 blocks -> single wave)

// ---------------- scratch (device globals; no runtime allocation) ----------
__device__ __align__(16) unsigned g_maskf[Bz * Tz];
__device__ __align__(16) float    g_tab_rec[1024 * Hz];
__device__ __align__(16) float    g_tab_inlo[32 * Hz];
__device__ __align__(16) float    g_tab_inhi[32 * Hz];
__device__ __align__(16) float    g_tab_cls[1024 * 2];

// ---------------- k0: build LUTs (12 parallel blocks), zero output ---------
__global__ void k0_tables(const float* __restrict__ w_in, const float* __restrict__ w_rec,
                          const float* __restrict__ w_cls, const float* __restrict__ b_cls,
                          float* __restrict__ out) {
    int m = threadIdx.x;           // 0..1023
    int bid = blockIdx.x;
    if (bid < Hz) {
        int o = bid;
        float a = 0.f;
        #pragma unroll
        for (int h = 0; h < Hz; h++)
            if ((m >> h) & 1) a += w_rec[o * Hz + h];   // same add order as before
        g_tab_rec[m * Hz + o] = a;
    } else if (bid == Hz) {
        #pragma unroll
        for (int o = 0; o < 2; o++) {
            float a = 0.f;
            #pragma unroll
            for (int h = 0; h < Hz; h++)
                if ((m >> h) & 1) a += w_cls[o * Hz + h];
            g_tab_cls[m * 2 + o] = a + b_cls[o];
        }
        if (m < Bz * 2) out[m] = 0.f;
    } else {
        if (m < 32) {
            #pragma unroll
            for (int o = 0; o < Hz; o++) {
                float lo = 0.f, hi = 0.f;
                #pragma unroll
                for (int h = 0; h < 5; h++) if ((m >> h) & 1) lo += w_in[o * Hz + h];
                #pragma unroll
                for (int h = 0; h < 5; h++) if ((m >> h) & 1) hi += w_in[o * Hz + 5 + h];
                g_tab_inlo[m * Hz + o] = lo;
                g_tab_inhi[m * Hz + o] = hi;
            }
        }
    }
}

// ---------------- k1: fused front GEMM + LIF (288 threads, one pass) -------
__global__ void __launch_bounds__(K1T) k1_front(const float* __restrict__ x,
                                                const float* __restrict__ w_front,
                                                const float* __restrict__ b_front) {
    __shared__ float ws[Hz * CINz];
    __shared__ float bs[Hz];
    __shared__ float sf[K1T * Hz];           // 2880 floats
    int tid = threadIdx.x, bt = blockIdx.x, b = blockIdx.y;
    for (int i = tid; i < Hz * CINz; i += K1T) ws[i] = w_front[i];
    if (tid < Hz) bs[tid] = b_front[tid];
    __syncthreads();

    // GEMM: exactly one t-row per thread (li == tid), no second pass
    {
        int t = bt * TCH - 32 + tid;
        if (t >= 0) {
            const float* xp = x + ((size_t)b * XCz + 1) * Tz + t;  // skip AUD ch 0
            float acc[Hz];
            #pragma unroll
            for (int h = 0; h < Hz; h++) acc[h] = 0.f;
            #pragma unroll 4
            for (int c = 0; c < CINz; c++) {
                float v = __ldg(xp + (size_t)c * Tz);
                #pragma unroll
                for (int h = 0; h < Hz; h++) acc[h] = fmaf(ws[h * CINz + c], v, acc[h]);
            }
            #pragma unroll
            for (int h = 0; h < Hz; h++) sf[tid * Hz + h] = acc[h] + bs[h];
        }
    }
    __syncthreads();

    int wid = tid >> 5, lane = tid & 31;
    if (wid < 2) {
        int seg = wid * 2 + (lane >> 4);     // 0..3
        int h  = lane & 15;
        int hc = (h < Hz) ? h : Hz - 1;
        int t0s = bt * TCH + seg * 64;
        int li0 = seg * 64 + 32;
        int lis = (t0s == 0) ? li0 : li0 - 32;
        float u = 0.f; bool o = false;
        for (int li = lis; li < li0; li++) {          // warmup (no output)
            float xv = sf[li * Hz + hc];
            u = o ? xv : fmaf(0.25f, u, xv);
            o = (h < Hz) && (u > 0.2f);
        }
        unsigned* mp = g_maskf + (size_t)b * Tz + t0s;
        for (int g = 0; g < 16; g++) {
            unsigned q0, q1, q2, q3;
            #pragma unroll
            for (int kk = 0; kk < 4; kk++) {
                int li = li0 + g * 4 + kk;
                float xv = sf[li * Hz + hc];
                u = o ? xv : fmaf(0.25f, u, xv);
                o = (h < Hz) && (u > 0.2f);
                unsigned bal = __ballot_sync(0xFFFFFFFFu, o);
                unsigned mk = (lane < 16) ? (bal & 0x3FFu) : ((bal >> 16) & 0x3FFu);
                if (kk == 0) q0 = mk; else if (kk == 1) q1 = mk;
                else if (kk == 2) q2 = mk; else q3 = mk;
            }
            if (lane == 0 || lane == 16)
                *(uint4*)(mp + g * 4) = make_uint4(q0, q1, q2, q3);
        }
    }
}

// ---------------- k2: segmented LSNN scan + fused classifier ---------------
// Critical chain: VOTE -> IMAD -> LDS(rec) -> FSETP -> VOTE (~123 cyc/step).
// Lanes 10/11 run the 2-neuron classifier LIF in the chain's shadow.
__global__ void __launch_bounds__(WPB * 32, 1) k2_scan(float* __restrict__ out) {
    __shared__ float s_rec[1024 * Hz];
    __shared__ float s_inlo[32 * Hz];
    __shared__ float s_inhi[32 * Hz];
    int tid = threadIdx.x, lane = tid & 31, wrp = tid >> 5;
    {
        const float4* src = (const float4*)g_tab_rec;
        float4* dst = (float4*)s_rec;
        for (int i = tid; i < (1024 * Hz) / 4; i += WPB * 32) dst[i] = src[i];
        for (int i = tid; i < 32 * Hz; i += WPB * 32) { s_inlo[i] = g_tab_inlo[i]; s_inhi[i] = g_tab_inhi[i]; }
    }
    __syncthreads();

    int w   = blockIdx.x * WPB + wrp;        // 0..Bz*NS2-1
    int b   = w >> 4;                        // NS2 = 16
    int seg = w & (NS2 - 1);
    int t0  = seg * SEGL2;
    int ts  = (t0 - WARM2 > 0) ? (t0 - WARM2) : 0;

    int ln = (lane < Hz) ? lane : 0;
    int csel = (lane == 11) ? 1 : 0;
    const uint4* mfp = (const uint4*)(g_maskf + (size_t)b * Tz);
    int js = ts >> 2, jw = t0 >> 2, je = (t0 + SEGL2) >> 2;

    float v = 0.f, ii = 0.f;
    unsigned mz = 0;
    float uc = 0.f; bool oc = false; int cnt = 0;
    uint4 c0 = mfp[js];
    uint4 c1 = mfp[js + 1];
    for (int j = js; j < je; j++) {
        int j2 = (j + 2 < je) ? j + 2 : je - 1;
        uint4 nxt = mfp[j2];
        bool counting = (j >= jw);
        unsigned mfs[4] = {c0.x, c0.y, c0.z, c0.w};
        #pragma unroll
        for (int k = 0; k < 4; k++) {
            unsigned mf = mfs[k];
            float xin = s_inlo[(mf & 31u) * Hz + ln] + s_inhi[((mf >> 5) & 31u) * Hz + ln];
            float pre = ii + xin;                          // off critical path
            float thr = fmaf(-9.0f, v, 2.0f) - pre;        // off critical path
            float rec = s_rec[mz * Hz + ln];               // critical LDS
            bool  z   = (rec > thr);                       // == (vdec > 0.2)
            mz = __ballot_sync(0xFFFFFFFFu, z) & 0x3FFu;   // critical VOTE
            // classifier LIF (lanes 10/11 meaningful) in the chain's shadow
            float xc = __ldg(&g_tab_cls[mz * 2 + csel]);   // 8KB table, L1-hot
            uc = oc ? xc : fmaf(0.25f, uc, xc);
            oc = (uc > 0.2f);
            if (counting && oc) cnt++;
            // LSNN state updates in the shadow of next step's LDS/VOTE
            float ij   = pre + rec;                        // i_jump
            float vdec = fmaf(0.1f, ij, 0.9f * v);
            ii = fmaf(-0.2f, ij, ij);                      // i_dec
            v  = z ? 0.f : vdec;
        }
        c0 = c1; c1 = nxt;
    }
    // counts * 2^-13: every partial sum exact in fp32 atomics
    if (lane == 10) atomicAdd(&out[b * 2 + 0], (float)cnt * (1.0f / (float)Tz));
    if (lane == 11) atomicAdd(&out[b * 2 + 1], (float)cnt * (1.0f / (float)Tz));
}

extern "C" void kernel_launch(void* const* d_in, const int* in_sizes, int n_in,
                              void* d_out, int out_size) {
    const float* x       = (const float*)d_in[0];
    const float* w_front = (const float*)d_in[1];
    const float* b_front = (const float*)d_in[2];
    const float* w_in    = (const float*)d_in[3];
    const float* w_rec   = (const float*)d_in[4];
    const float* w_cls   = (const float*)d_in[5];
    const float* b_cls   = (const float*)d_in[6];
    float* out = (float*)d_out;

    k0_tables<<<Hz + 2, 1024>>>(w_in, w_rec, w_cls, b_cls, out);
    k1_front<<<dim3(Tz / TCH, Bz), K1T>>>(x, w_front, b_front);
    k2_scan<<<(Bz * NS2) / WPB, WPB * 32>>>(out);
}

// round 8
// speedup vs baseline: 2.2770x; 1.0531x over previous
#include <cuda_runtime.h>
#include <cstdint>

#define Bz   64
#define Tz   8192
#define Hz   10
#define CINz 64
#define XCz  66
// front LIF segmentation (decay 0.25 -> 32-step warmup exact)
#define TCH  256           // t-chunk per k1 block (4 segments of 64)
#define K1T  (TCH + 32)    // 288 threads: one GEMM row each
// LSNN segmentation: 16 segments of 512, warmup 2048 (segs 0-4 exact)
#define NS2   16
#define SEGL2 512
#define WARM2 2048
#define WPB   8            // warps per block in k2 (128 blocks -> single wave)

// ---------------- scratch (device global; no runtime allocation) -----------
__device__ __align__(16) unsigned g_maskf[Bz * Tz];

// ---------------- k1: fused front GEMM + LIF (288 threads, one pass) -------
__global__ void __launch_bounds__(K1T, 5) k1_front(const float* __restrict__ x,
                                                   const float* __restrict__ w_front,
                                                   const float* __restrict__ b_front,
                                                   float* __restrict__ out) {
    __shared__ __align__(16) float wsT[CINz * 12];   // transposed, padded to 12/c
    __shared__ float bs[Hz];
    __shared__ float sf[K1T * Hz];                   // 2880 floats
    int tid = threadIdx.x, bt = blockIdx.x, b = blockIdx.y;

    // zero the output accumulator once (k1 precedes k2 in-stream)
    if (bt == 0 && b == 0 && tid < Bz * 2) out[tid] = 0.f;

    for (int i = tid; i < CINz * 12; i += K1T) {
        int c = i / 12, h = i - c * 12;
        wsT[i] = (h < Hz) ? w_front[h * CINz + c] : 0.f;
    }
    if (tid < Hz) bs[tid] = b_front[tid];
    __syncthreads();

    // GEMM: one t-row per thread; 3 LDS.128 + 4 LDG + 40 FMA per 4-c group
    {
        int t = bt * TCH - 32 + tid;
        if (t >= 0) {
            const float* xp = x + ((size_t)b * XCz + 1) * Tz + t;  // skip AUD ch 0
            float acc[Hz];
            #pragma unroll
            for (int h = 0; h < Hz; h++) acc[h] = 0.f;
            for (int c0 = 0; c0 < CINz; c0 += 4) {
                float xv[4];
                #pragma unroll
                for (int q = 0; q < 4; q++) xv[q] = __ldg(xp + (size_t)(c0 + q) * Tz);
                #pragma unroll
                for (int q = 0; q < 4; q++) {
                    const float4* wr = (const float4*)(wsT + (c0 + q) * 12);
                    float4 w0 = wr[0], w1 = wr[1];
                    float2 w2 = *(const float2*)(wsT + (c0 + q) * 12 + 8);
                    acc[0] = fmaf(w0.x, xv[q], acc[0]);
                    acc[1] = fmaf(w0.y, xv[q], acc[1]);
                    acc[2] = fmaf(w0.z, xv[q], acc[2]);
                    acc[3] = fmaf(w0.w, xv[q], acc[3]);
                    acc[4] = fmaf(w1.x, xv[q], acc[4]);
                    acc[5] = fmaf(w1.y, xv[q], acc[5]);
                    acc[6] = fmaf(w1.z, xv[q], acc[6]);
                    acc[7] = fmaf(w1.w, xv[q], acc[7]);
                    acc[8] = fmaf(w2.x, xv[q], acc[8]);
                    acc[9] = fmaf(w2.y, xv[q], acc[9]);
                }
            }
            #pragma unroll
            for (int h = 0; h < Hz; h++) sf[tid * Hz + h] = acc[h] + bs[h];
        }
    }
    __syncthreads();

    int wid = tid >> 5, lane = tid & 31;
    if (wid < 2) {
        int seg = wid * 2 + (lane >> 4);     // 0..3
        int h  = lane & 15;
        int hc = (h < Hz) ? h : Hz - 1;
        int t0s = bt * TCH + seg * 64;
        int li0 = seg * 64 + 32;
        int lis = (t0s == 0) ? li0 : li0 - 32;
        float u = 0.f; bool o = false;
        for (int li = lis; li < li0; li++) {          // warmup (no output)
            float xv = sf[li * Hz + hc];
            u = o ? xv : fmaf(0.25f, u, xv);
            o = (h < Hz) && (u > 0.2f);
        }
        unsigned* mp = g_maskf + (size_t)b * Tz + t0s;
        for (int g = 0; g < 16; g++) {
            unsigned q0, q1, q2, q3;
            #pragma unroll
            for (int kk = 0; kk < 4; kk++) {
                int li = li0 + g * 4 + kk;
                float xv = sf[li * Hz + hc];
                u = o ? xv : fmaf(0.25f, u, xv);
                o = (h < Hz) && (u > 0.2f);
                unsigned bal = __ballot_sync(0xFFFFFFFFu, o);
                unsigned mk = (lane < 16) ? (bal & 0x3FFu) : ((bal >> 16) & 0x3FFu);
                if (kk == 0) q0 = mk; else if (kk == 1) q1 = mk;
                else if (kk == 2) q2 = mk; else q3 = mk;
            }
            if (lane == 0 || lane == 16)
                *(uint4*)(mp + g * 4) = make_uint4(q0, q1, q2, q3);
        }
    }
}

// ---------------- k2: segmented LSNN scan + fused classifier ---------------
// Tables built in-block from raw weights (same add order as before -> bit-identical).
// Critical chain: VOTE -> IMAD -> LDS(rec) -> FSETP -> VOTE (~119 cyc/step).
// Lanes 10/11 run the 2-neuron classifier LIF in the chain's shadow.
__global__ void __launch_bounds__(WPB * 32, 1) k2_scan(const float* __restrict__ w_in,
                                                       const float* __restrict__ w_rec,
                                                       const float* __restrict__ w_cls,
                                                       const float* __restrict__ b_cls,
                                                       float* __restrict__ out) {
    __shared__ float s_rec[1024 * Hz];
    __shared__ float s_cls[1024 * 2];
    __shared__ float s_inlo[32 * Hz];
    __shared__ float s_inhi[32 * Hz];
    int tid = threadIdx.x, lane = tid & 31, wrp = tid >> 5;

    // ---- prologue: build LUTs (each block, in smem) ----
    {
        float wr[Hz * Hz];
        #pragma unroll
        for (int i = 0; i < Hz * Hz; i++) wr[i] = __ldg(&w_rec[i]);
        float wc0[Hz], wc1[Hz];
        #pragma unroll
        for (int h = 0; h < Hz; h++) { wc0[h] = __ldg(&w_cls[h]); wc1[h] = __ldg(&w_cls[Hz + h]); }
        float bc0 = __ldg(&b_cls[0]), bc1 = __ldg(&b_cls[1]);
        for (int m = tid; m < 1024; m += WPB * 32) {
            #pragma unroll
            for (int o = 0; o < Hz; o++) {
                float a = 0.f;
                #pragma unroll
                for (int h = 0; h < Hz; h++)
                    if ((m >> h) & 1) a += wr[o * Hz + h];
                s_rec[m * Hz + o] = a;
            }
            float a0 = 0.f, a1 = 0.f;
            #pragma unroll
            for (int h = 0; h < Hz; h++)
                if ((m >> h) & 1) { a0 += wc0[h]; a1 += wc1[h]; }
            s_cls[m * 2 + 0] = a0 + bc0;
            s_cls[m * 2 + 1] = a1 + bc1;
        }
        if (tid < 32) {
            #pragma unroll
            for (int o = 0; o < Hz; o++) {
                float lo = 0.f, hi = 0.f;
                #pragma unroll
                for (int h = 0; h < 5; h++) if ((tid >> h) & 1) lo += __ldg(&w_in[o * Hz + h]);
                #pragma unroll
                for (int h = 0; h < 5; h++) if ((tid >> h) & 1) hi += __ldg(&w_in[o * Hz + 5 + h]);
                s_inlo[tid * Hz + o] = lo;
                s_inhi[tid * Hz + o] = hi;
            }
        }
    }
    __syncthreads();

    int w   = blockIdx.x * WPB + wrp;        // 0..Bz*NS2-1
    int b   = w >> 4;                        // NS2 = 16
    int seg = w & (NS2 - 1);
    int t0  = seg * SEGL2;
    int ts  = (t0 - WARM2 > 0) ? (t0 - WARM2) : 0;

    int ln = (lane < Hz) ? lane : 0;
    int csel = (lane == 11) ? 1 : 0;
    const uint4* mfp = (const uint4*)(g_maskf + (size_t)b * Tz);
    int js = ts >> 2, jw = t0 >> 2, je = (t0 + SEGL2) >> 2;

    float v = 0.f, ii = 0.f;
    unsigned mz = 0;
    float uc = 0.f; bool oc = false; int cnt = 0;
    uint4 c0 = mfp[js];
    uint4 c1 = mfp[js + 1];
    for (int j = js; j < je; j++) {
        int j2 = (j + 2 < je) ? j + 2 : je - 1;
        uint4 nxt = mfp[j2];
        bool counting = (j >= jw);
        unsigned mfs[4] = {c0.x, c0.y, c0.z, c0.w};
        #pragma unroll
        for (int k = 0; k < 4; k++) {
            unsigned mf = mfs[k];
            float xin = s_inlo[(mf & 31u) * Hz + ln] + s_inhi[((mf >> 5) & 31u) * Hz + ln];
            float pre = ii + xin;                          // off critical path
            float thr = fmaf(-9.0f, v, 2.0f) - pre;        // off critical path
            float rec = s_rec[mz * Hz + ln];               // critical LDS
            bool  z   = (rec > thr);                       // == (vdec > 0.2)
            mz = __ballot_sync(0xFFFFFFFFu, z) & 0x3FFu;   // critical VOTE
            // classifier LIF (lanes 10/11 meaningful) in the chain's shadow
            float xc = s_cls[mz * 2 + csel];
            uc = oc ? xc : fmaf(0.25f, uc, xc);
            oc = (uc > 0.2f);
            if (counting && oc) cnt++;
            // LSNN state updates in the shadow of next step's LDS/VOTE
            float ij   = pre + rec;                        // i_jump
            float vdec = fmaf(0.1f, ij, 0.9f * v);
            ii = fmaf(-0.2f, ij, ij);                      // i_dec
            v  = z ? 0.f : vdec;
        }
        c0 = c1; c1 = nxt;
    }
    // counts * 2^-13: every partial sum exact in fp32 atomics
    if (lane == 10) atomicAdd(&out[b * 2 + 0], (float)cnt * (1.0f / (float)Tz));
    if (lane == 11) atomicAdd(&out[b * 2 + 1], (float)cnt * (1.0f / (float)Tz));
}

extern "C" void kernel_launch(void* const* d_in, const int* in_sizes, int n_in,
                              void* d_out, int out_size) {
    const float* x       = (const float*)d_in[0];
    const float* w_front = (const float*)d_in[1];
    const float* b_front = (const float*)d_in[2];
    const float* w_in    = (const float*)d_in[3];
    const float* w_rec   = (const float*)d_in[4];
    const float* w_cls   = (const float*)d_in[5];
    const float* b_cls   = (const float*)d_in[6];
    float* out = (float*)d_out;

    k1_front<<<dim3(Tz / TCH, Bz), K1T>>>(x, w_front, b_front, out);
    k2_scan<<<(Bz * NS2) / WPB, WPB * 32>>>(w_in, w_rec, w_cls, b_cls, out);
}